// round 16
// baseline (speedup 1.0000x reference)
#include <cuda_runtime.h>
#include <cuda_bf16.h>
#include <math.h>
#include <stdint.h>

#define DIM 384
#define TOKENS 8192
#define HID 1536
#define HEADS 6

// ---------------- scratch (device globals; no allocations allowed) ----------
__device__ float g_y[TOKENS * DIM];
__device__ float g_attn[TOKENS * DIM];
__device__ float g_res[TOKENS * DIM];
__device__ float g_h[TOKENS * HID];
// attention-native qkv layouts (all bf16)
__device__ __nv_bfloat16 g_qs[2 * HEADS * 4096 * 64];   // [b,h,tok,d] scaled q
__device__ __nv_bfloat16 g_ks[2 * HEADS * 4096 * 64];   // [b,h,tok,d]
__device__ __nv_bfloat16 g_vt[2 * HEADS * 64 * 4096];   // [b,h,d,kv]
// pre-rounded (tf32) weights: qkv_w | proj_w | fc1_w | fc2_w
#define W_QKV_OFF 0
#define W_PROJ_OFF 442368
#define W_FC1_OFF (442368 + 147456)
#define W_FC2_OFF (442368 + 147456 + 589824)
#define W_TOTAL (442368 + 147456 + 589824 + 589824)
__device__ float g_w[W_TOTAL];

// ---------------- helpers ------------------------------------------------------
__device__ __forceinline__ uint32_t f2tf(float x) {
    uint32_t u;
    asm("cvt.rna.tf32.f32 %0, %1;" : "=r"(u) : "f"(x));
    return u;
}
__device__ __forceinline__ float rnd_tf(float x) {
    return __uint_as_float(f2tf(x));
}
__device__ __forceinline__ uint32_t pack_bf2(float lo, float hi) {
    uint32_t r;
    asm("cvt.rn.bf16x2.f32 %0, %1, %2;" : "=r"(r) : "f"(hi), "f"(lo));
    return r;
}

__device__ __forceinline__ uint32_t smem_u32(const void* p) {
    uint32_t a;
    asm("{ .reg .u64 t; cvta.to.shared.u64 t, %1; cvt.u32.u64 %0, t; }"
        : "=r"(a) : "l"(p));
    return a;
}

__device__ __forceinline__ void mma_tf32(float c[4], const uint32_t a[4],
                                         const uint32_t b[2]) {
    asm volatile(
        "mma.sync.aligned.m16n8k8.row.col.f32.tf32.tf32.f32 "
        "{%0,%1,%2,%3}, {%4,%5,%6,%7}, {%8,%9}, {%0,%1,%2,%3};"
        : "+f"(c[0]), "+f"(c[1]), "+f"(c[2]), "+f"(c[3])
        : "r"(a[0]), "r"(a[1]), "r"(a[2]), "r"(a[3]), "r"(b[0]), "r"(b[1]));
}
__device__ __forceinline__ void mma_bf16(float c[4], const uint32_t a[4],
                                         const uint32_t b[2]) {
    asm volatile(
        "mma.sync.aligned.m16n8k16.row.col.f32.bf16.bf16.f32 "
        "{%0,%1,%2,%3}, {%4,%5,%6,%7}, {%8,%9}, {%0,%1,%2,%3};"
        : "+f"(c[0]), "+f"(c[1]), "+f"(c[2]), "+f"(c[3])
        : "r"(a[0]), "r"(a[1]), "r"(a[2]), "r"(a[3]), "r"(b[0]), "r"(b[1]));
}
__device__ __forceinline__ void ldsm4(uint32_t r[4], uint32_t addr) {
    asm volatile(
        "ldmatrix.sync.aligned.m8n8.x4.shared.b16 {%0,%1,%2,%3}, [%4];"
        : "=r"(r[0]), "=r"(r[1]), "=r"(r[2]), "=r"(r[3]) : "r"(addr));
}

// ---------------- fused weight pre-round (single launch) ----------------------
__global__ void round_w_all(const float* __restrict__ w0, const float* __restrict__ w1,
                            const float* __restrict__ w2, const float* __restrict__ w3,
                            float* __restrict__ out) {
    int i = blockIdx.x * 256 + threadIdx.x;  // float4 index
    const int n0 = W_PROJ_OFF / 4, n1 = W_FC1_OFF / 4, n2 = W_FC2_OFF / 4,
              n3 = W_TOTAL / 4;
    if (i >= n3) return;
    float4 v;
    if (i < n0)      v = ((const float4*)w0)[i];
    else if (i < n1) v = ((const float4*)w1)[i - n0];
    else if (i < n2) v = ((const float4*)w2)[i - n1];
    else             v = ((const float4*)w3)[i - n2];
    ((float4*)out)[i] =
        make_float4(rnd_tf(v.x), rnd_tf(v.y), rnd_tf(v.z), rnd_tf(v.w));
}

// ---------------- LayerNorm (outputs tf32-rounded: feeds GEMM A operand) ------
__global__ void ln_kernel(const float* __restrict__ in, const float* __restrict__ w,
                          const float* __restrict__ b, float* __restrict__ out) {
    int row = blockIdx.x;
    const float* x = in + (size_t)row * DIM;
    int t = threadIdx.x;  // 128
    float v0 = x[t], v1 = x[t + 128], v2 = x[t + 256];
    float s = v0 + v1 + v2;
    float q = v0 * v0 + v1 * v1 + v2 * v2;
#pragma unroll
    for (int off = 16; off; off >>= 1) {
        s += __shfl_xor_sync(0xffffffffu, s, off);
        q += __shfl_xor_sync(0xffffffffu, q, off);
    }
    __shared__ float ss[4], sq[4];
    int wid = t >> 5, lane = t & 31;
    if (lane == 0) { ss[wid] = s; sq[wid] = q; }
    __syncthreads();
    s = ss[0] + ss[1] + ss[2] + ss[3];
    q = sq[0] + sq[1] + sq[2] + sq[3];
    float mean = s * (1.0f / DIM);
    float var = q * (1.0f / DIM) - mean * mean;
    float rstd = rsqrtf(var + 1e-5f);
    float* o = out + (size_t)row * DIM;
    o[t]       = rnd_tf((v0 - mean) * rstd * w[t]       + b[t]);
    o[t + 128] = rnd_tf((v1 - mean) * rstd * w[t + 128] + b[t + 128]);
    o[t + 256] = rnd_tf((v2 - mean) * rstd * w[t + 256] + b[t + 256]);
}

// ---------------- cp.async tf32 GEMM: C = A[M,K] * B[N,K]^T (+epi) -----------
enum { EPI_QKV = 0, EPI_BIAS_RES = 1, EPI_GELU = 2, EPI_OUT2 = 3 };

#define GBM 128
#define GBN 128
#define GBK 32
#define GSTAGES 3
#define GBOFF (GBM * 36 * 4)
#define GSTRIDE ((GBM + GBN) * 36 * 4)
#define GEMM_SMEM (GSTAGES * GSTRIDE)

template <int EPI>
__global__ void __launch_bounds__(256, 2)
gemm_cp(const float* __restrict__ A, const float* __restrict__ B,
        const float* __restrict__ bias, const float* __restrict__ res,
        float* __restrict__ C, __nv_bfloat16* __restrict__ Cq,
        __nv_bfloat16* __restrict__ Ck, __nv_bfloat16* __restrict__ Cv,
        int M, int N, int K) {
    extern __shared__ char smem[];
    uint32_t sb = smem_u32(smem);
    int tid = threadIdx.x;
    int bm = blockIdx.y * GBM, bn = blockIdx.x * GBN;
    int wid = tid >> 5, lane = tid & 31;
    int wm = (wid & 1) * 64, wn = (wid >> 1) * 32;
    int g = lane >> 2, t4 = lane & 3;

    int lr = tid >> 3;
    int lq = (tid & 7) * 4;

    const float* Ap = A + (size_t)(bm + lr) * K + lq;
    const float* Bp = B + (size_t)(bn + lr) * K + lq;
    uint32_t dA = sb + (uint32_t)(lr * 36 + lq) * 4;
    uint32_t dB = sb + GBOFF + (uint32_t)(lr * 36 + lq) * 4;

    const int S = K / GBK;

#define G_ISSUE(st)                                                            \
    do {                                                                       \
        uint32_t off = (uint32_t)((st) % GSTAGES) * GSTRIDE;                   \
        int k0 = (st) * GBK;                                                   \
        _Pragma("unroll")                                                      \
        for (int i = 0; i < 4; i++)                                            \
            asm volatile("cp.async.cg.shared.global [%0], [%1], 16;"           \
                         :: "r"(dA + off + (uint32_t)(i * 32 * 36 * 4)),       \
                            "l"(Ap + (size_t)(32 * i) * K + k0) : "memory");   \
        _Pragma("unroll")                                                      \
        for (int i = 0; i < 4; i++)                                            \
            asm volatile("cp.async.cg.shared.global [%0], [%1], 16;"           \
                         :: "r"(dB + off + (uint32_t)(i * 32 * 36 * 4)),       \
                            "l"(Bp + (size_t)(32 * i) * K + k0) : "memory");   \
        asm volatile("cp.async.commit_group;" ::: "memory");                   \
    } while (0)

    G_ISSUE(0);
    G_ISSUE(1);

    float c[4][4][4] = {};

    for (int s = 0; s < S; s++) {
        asm volatile("cp.async.wait_group %0;" :: "n"(GSTAGES - 2) : "memory");
        __syncthreads();
        if (s + GSTAGES - 1 < S) G_ISSUE(s + GSTAGES - 1);

        const float(*As)[36] =
            (const float(*)[36])(smem + (s % GSTAGES) * GSTRIDE);
        const float(*Bs)[36] =
            (const float(*)[36])(smem + (s % GSTAGES) * GSTRIDE + GBOFF);

#pragma unroll
        for (int ks = 0; ks < 4; ks++) {
            int kk = ks * 8;
            uint32_t a[4][4], b[4][2];
#pragma unroll
            for (int im = 0; im < 4; im++) {
                int m = wm + im * 16 + g;
                a[im][0] = __float_as_uint(As[m][kk + t4]);
                a[im][1] = __float_as_uint(As[m + 8][kk + t4]);
                a[im][2] = __float_as_uint(As[m][kk + t4 + 4]);
                a[im][3] = __float_as_uint(As[m + 8][kk + t4 + 4]);
            }
#pragma unroll
            for (int jn = 0; jn < 4; jn++) {
                int n = wn + jn * 8 + g;
                b[jn][0] = __float_as_uint(Bs[n][kk + t4]);
                b[jn][1] = __float_as_uint(Bs[n][kk + t4 + 4]);
            }
#pragma unroll
            for (int im = 0; im < 4; im++)
#pragma unroll
                for (int jn = 0; jn < 4; jn++) mma_tf32(c[im][jn], a[im], b[jn]);
        }
    }

    // epilogue
#pragma unroll
    for (int im = 0; im < 4; im++) {
#pragma unroll
        for (int half = 0; half < 2; half++) {
            int row = bm + wm + im * 16 + g + half * 8;
#pragma unroll
            for (int jn = 0; jn < 4; jn++) {
                int col = bn + wn + jn * 8 + t4 * 2;
                float v0 = c[im][jn][2 * half];
                float v1 = c[im][jn][2 * half + 1];
                if (EPI == EPI_QKV) {
                    int b = row >> 12, tok = row & 4095;
                    if (col < 768) {
                        bool isq = col < 384;
                        float sc = isq ? 0.125f : 1.0f;
                        int cc = isq ? col : col - 384;
                        int h = cc >> 6, d = cc & 63;
                        __nv_bfloat16* dst = isq ? Cq : Ck;
                        *(uint32_t*)&dst[(((size_t)b * HEADS + h) * 4096 + tok) * 64 + d] =
                            pack_bf2(v0 * sc, v1 * sc);
                    } else {
                        int cc = col - 768;
                        int h = cc >> 6, d = cc & 63;
                        size_t base = (((size_t)b * HEADS + h) * 64 + d) * 4096 + tok;
                        Cv[base]        = __float2bfloat16(v0);
                        Cv[base + 4096] = __float2bfloat16(v1);
                    }
                    continue;
                } else if (EPI == EPI_BIAS_RES) {
                    v0 += bias[col]     + res[(size_t)row * N + col];
                    v1 += bias[col + 1] + res[(size_t)row * N + col + 1];
                } else if (EPI == EPI_GELU) {
                    v0 += bias[col];
                    v1 += bias[col + 1];
                    v0 = rnd_tf(0.5f * v0 * (1.0f + erff(v0 * 0.70710678118654752f)));
                    v1 = rnd_tf(0.5f * v1 * (1.0f + erff(v1 * 0.70710678118654752f)));
                } else if (EPI == EPI_OUT2) {
                    v0 = 2.0f * (v0 + bias[col]);
                    v1 = 2.0f * (v1 + bias[col + 1]);
                }
                *(float2*)&C[(size_t)row * N + col] = make_float2(v0, v1);
            }
        }
    }
}

// ---------------- flash attention v4: 64q CTA, 4 warps x 16q, register P -----
// Finer CTA granularity: 768 CTAs (better wave balance), ~100 regs/thread ->
// 4 CTAs/SM = 16 warps/SM (4/SMSP). P stays register-resident; ldmatrix frags.
#define AT_QS 0                           // 64*144 = 9216
#define AT_KS 9216                        // 2 * 9216
#define AT_VT (9216 + 18432)              // 2 * 9216
#define ATTN_SMEM (AT_VT + 18432)         // 46080

__global__ void __launch_bounds__(128, 4)
attn_tc(const __nv_bfloat16* __restrict__ qg, const __nv_bfloat16* __restrict__ kg,
        const __nv_bfloat16* __restrict__ vg, float* __restrict__ out) {
    extern __shared__ char sm[];
    uint32_t sb = smem_u32(sm);
    uint16_t* Qs = (uint16_t*)(sm + AT_QS);

    int bh = blockIdx.y;
    int b = bh / HEADS, h = bh % HEADS;
    int q0 = blockIdx.x * 64;
    int tid = threadIdx.x;
    int wid = tid >> 5, lane = tid & 31;
    int wm = wid * 16;  // 16 q rows per warp
    int g = lane >> 2, t4 = lane & 3;

    const __nv_bfloat16* qb = qg + (((size_t)bh * 4096) + q0) * 64;
    const __nv_bfloat16* kb = kg + (size_t)bh * 4096 * 64;
    const __nv_bfloat16* vb = vg + (size_t)bh * 64 * 4096;

    // stage Q (64 rows x 64 bf16, rows padded to 72 halves)
#pragma unroll
    for (int i = 0; i < 4; i++) {
        int chunk = tid + 128 * i;
        int row = chunk >> 3, c8 = (chunk & 7) * 8;
        *(uint4*)(Qs + row * 72 + c8) = *(const uint4*)(qb + row * 64 + c8);
    }

    // cp.async staging of K / Vt bf16 64x64 tiles, double-buffered
    int srow = tid >> 1, shalf = tid & 1;
    uint32_t kdst = sb + AT_KS + (uint32_t)(srow * 144 + shalf * 64);
    const __nv_bfloat16* ksrc0 = kb + (size_t)srow * 64 + shalf * 32;
    uint32_t vdst = sb + AT_VT + (uint32_t)(srow * 144 + shalf * 64);
    const __nv_bfloat16* vsrc0 = vb + (size_t)srow * 4096 + shalf * 32;

#define AT_ISSUE(kt, p)                                                        \
    do {                                                                       \
        const __nv_bfloat16* ks_ = ksrc0 + (size_t)(kt) * 64 * 64;             \
        uint32_t kd_ = kdst + (uint32_t)(p) * 9216u;                           \
        const __nv_bfloat16* vs_ = vsrc0 + (size_t)(kt) * 64;                  \
        uint32_t vd_ = vdst + (uint32_t)(p) * 9216u;                           \
        _Pragma("unroll")                                                      \
        for (int i = 0; i < 4; i++) {                                          \
            asm volatile("cp.async.cg.shared.global [%0], [%1], 16;"           \
                         :: "r"(kd_ + (uint32_t)(i * 16)),                     \
                            "l"(ks_ + i * 8) : "memory");                      \
            asm volatile("cp.async.cg.shared.global [%0], [%1], 16;"           \
                         :: "r"(vd_ + (uint32_t)(i * 16)),                     \
                            "l"(vs_ + i * 8) : "memory");                      \
        }                                                                      \
        asm volatile("cp.async.commit_group;" ::: "memory");                   \
    } while (0)

    AT_ISSUE(0, 0);
    __syncthreads();  // Q staged

    // ldmatrix lane offsets (rows * 144B, col-halves * 2B)
    uint32_t aoff = (uint32_t)(((lane & 7) + ((lane >> 3) & 1) * 8) * 144 +
                               (lane >> 4) * 16);
    uint32_t boff = (uint32_t)((((lane >> 4) & 1) * 8 + (lane & 7)) * 144 +
                               ((lane >> 3) & 1) * 16);

    // load Q fragments once (tile-invariant): qa[ks][4]
    uint32_t qa[4][4];
#pragma unroll
    for (int ks = 0; ks < 4; ks++)
        ldsm4(qa[ks], sb + AT_QS + (uint32_t)(wm * 144 + ks * 32) + aoff);

    float o[8][4] = {};
    float lacc[2] = {};

    for (int kt = 0; kt < 64; kt++) {
        int p = kt & 1;
        asm volatile("cp.async.wait_group 0;" ::: "memory");
        __syncthreads();  // tile kt ready; prev tile's reads done everywhere
        if (kt < 63) AT_ISSUE(kt + 1, p ^ 1);

        uint32_t kbase = sb + AT_KS + (uint32_t)p * 9216u + boff;
        uint32_t vbase = sb + AT_VT + (uint32_t)p * 9216u + boff;

#pragma unroll
        for (int qq = 0; qq < 4; qq++) {  // kv quarter: cols 16*qq..+15
            // ---- S = Q K^T for this quarter ----
            float scq[2][4] = {};
#pragma unroll
            for (int ks = 0; ks < 4; ks++) {
                uint32_t kb4[4];
                ldsm4(kb4, kbase + (uint32_t)(qq * 16 * 144 + ks * 32));
                mma_bf16(scq[0], qa[ks], kb4 + 0);
                mma_bf16(scq[1], qa[ks], kb4 + 2);
            }
            // ---- exp + pack to PV A-frags (registers only) ----
            uint32_t pp[4];
#pragma unroll
            for (int jl = 0; jl < 2; jl++) {
                float e0 = __expf(scq[jl][0]);
                float e1 = __expf(scq[jl][1]);
                float e2 = __expf(scq[jl][2]);
                float e3 = __expf(scq[jl][3]);
                lacc[0] += e0 + e1;
                lacc[1] += e2 + e3;
                pp[jl * 2 + 0] = pack_bf2(e0, e1);   // row g
                pp[jl * 2 + 1] = pack_bf2(e2, e3);   // row g+8
            }
            // ---- O += P V for this quarter (kv kstep = qq) ----
#pragma unroll
            for (int dj = 0; dj < 4; dj++) {  // d-group pairs (2dj, 2dj+1)
                uint32_t vb4[4];
                ldsm4(vb4, vbase + (uint32_t)(dj * 16 * 144 + qq * 32));
                mma_bf16(o[2 * dj + 0], pp, vb4 + 0);
                mma_bf16(o[2 * dj + 1], pp, vb4 + 2);
            }
        }
    }

    // deferred row-sum quad reduction (rows are warp-private)
#pragma unroll
    for (int hf = 0; hf < 2; hf++) {
        float s = lacc[hf];
        s += __shfl_xor_sync(0xffffffffu, s, 1);
        s += __shfl_xor_sync(0xffffffffu, s, 2);
        lacc[hf] = s;
    }

    // epilogue: normalize, pre-round (feeds proj GEMM A), write [B,N,C]
#pragma unroll
    for (int hf = 0; hf < 2; hf++) {
        int row = q0 + wm + g + hf * 8;
        float inv = 1.0f / lacc[hf];
#pragma unroll
        for (int dg = 0; dg < 8; dg++) {
            int col = h * 64 + dg * 8 + t4 * 2;
            float v0 = rnd_tf(o[dg][2 * hf] * inv);
            float v1 = rnd_tf(o[dg][2 * hf + 1] * inv);
            *(float2*)&out[((size_t)b * 4096 + row) * DIM + col] =
                make_float2(v0, v1);
        }
    }
}

// ---------------- launch --------------------------------------------------------
extern "C" void kernel_launch(void* const* d_in, const int* in_sizes, int n_in,
                              void* d_out, int out_size) {
    (void)in_sizes; (void)n_in; (void)out_size;
    const float* x      = (const float*)d_in[0];
    const float* qkv_w  = (const float*)d_in[1];
    const float* proj_w = (const float*)d_in[2];
    const float* proj_b = (const float*)d_in[3];
    const float* ln1_w  = (const float*)d_in[4];
    const float* ln1_b  = (const float*)d_in[5];
    const float* ln2_w  = (const float*)d_in[6];
    const float* ln2_b  = (const float*)d_in[7];
    const float* fc1_w  = (const float*)d_in[8];
    const float* fc1_b  = (const float*)d_in[9];
    const float* fc2_w  = (const float*)d_in[10];
    const float* fc2_b  = (const float*)d_in[11];
    float* out = (float*)d_out;

    float *y, *attn, *res, *hbuf, *wbuf;
    __nv_bfloat16 *qs, *ks, *vt;
    cudaGetSymbolAddress((void**)&y, g_y);
    cudaGetSymbolAddress((void**)&attn, g_attn);
    cudaGetSymbolAddress((void**)&res, g_res);
    cudaGetSymbolAddress((void**)&hbuf, g_h);
    cudaGetSymbolAddress((void**)&wbuf, g_w);
    cudaGetSymbolAddress((void**)&qs, g_qs);
    cudaGetSymbolAddress((void**)&ks, g_ks);
    cudaGetSymbolAddress((void**)&vt, g_vt);

    float* w_qkv  = wbuf + W_QKV_OFF;
    float* w_proj = wbuf + W_PROJ_OFF;
    float* w_fc1  = wbuf + W_FC1_OFF;
    float* w_fc2  = wbuf + W_FC2_OFF;

    cudaFuncSetAttribute(attn_tc, cudaFuncAttributeMaxDynamicSharedMemorySize,
                         ATTN_SMEM);
    cudaFuncSetAttribute(gemm_cp<EPI_QKV>,
                         cudaFuncAttributeMaxDynamicSharedMemorySize, GEMM_SMEM);
    cudaFuncSetAttribute(gemm_cp<EPI_BIAS_RES>,
                         cudaFuncAttributeMaxDynamicSharedMemorySize, GEMM_SMEM);
    cudaFuncSetAttribute(gemm_cp<EPI_GELU>,
                         cudaFuncAttributeMaxDynamicSharedMemorySize, GEMM_SMEM);
    cudaFuncSetAttribute(gemm_cp<EPI_OUT2>,
                         cudaFuncAttributeMaxDynamicSharedMemorySize, GEMM_SMEM);

    // 0) pre-round all weights to tf32 in one launch
    round_w_all<<<(W_TOTAL / 4 + 255) / 256, 256>>>(qkv_w, proj_w, fc1_w, fc2_w,
                                                    wbuf);

    // 1) LN1 (rounded out)
    ln_kernel<<<TOKENS, 128>>>(x, ln1_w, ln1_b, y);
    // 2) qkv = y @ qkv_w^T -> q[b,h,t,d] bf16 (scaled), k[b,h,t,d] bf16, vt[b,h,d,t] bf16
    gemm_cp<EPI_QKV><<<dim3(1152 / GBN, TOKENS / GBM), 256, GEMM_SMEM>>>(
        y, w_qkv, nullptr, nullptr, nullptr, qs, ks, vt, TOKENS, 3 * DIM, DIM);
    // 3) flash attention -> g_attn (rounded out)
    attn_tc<<<dim3(64, 12), 128, ATTN_SMEM>>>(qs, ks, vt, attn);
    // 4) res = x + attn @ proj_w^T + proj_b
    gemm_cp<EPI_BIAS_RES><<<dim3(DIM / GBN, TOKENS / GBM), 256, GEMM_SMEM>>>(
        attn, w_proj, proj_b, x, res, nullptr, nullptr, nullptr, TOKENS, DIM, DIM);
    // 5) LN2 (rounded out)
    ln_kernel<<<TOKENS, 128>>>(res, ln2_w, ln2_b, y);
    // 6) h = gelu(y @ fc1_w^T + fc1_b)  (rounded out)
    gemm_cp<EPI_GELU><<<dim3(HID / GBN, TOKENS / GBM), 256, GEMM_SMEM>>>(
        y, w_fc1, fc1_b, nullptr, hbuf, nullptr, nullptr, nullptr, TOKENS, HID, DIM);
    // 7) out = 2 * (h @ fc2_w^T + fc2_b)
    gemm_cp<EPI_OUT2><<<dim3(DIM / GBN, TOKENS / GBM), 256, GEMM_SMEM>>>(
        hbuf, w_fc2, fc2_b, nullptr, out, nullptr, nullptr, nullptr, TOKENS, DIM, HID);
}

// round 17
// speedup vs baseline: 1.0672x; 1.0672x over previous
#include <cuda_runtime.h>
#include <cuda_bf16.h>
#include <math.h>
#include <stdint.h>

#define DIM 384
#define TOKENS 8192
#define HID 1536
#define HEADS 6
#define KSPLIT 2

// ---------------- scratch (device globals; no allocations allowed) ----------
__device__ float g_y[TOKENS * DIM];
__device__ float g_attn[TOKENS * DIM];
__device__ float g_res[TOKENS * DIM];
__device__ float g_h[TOKENS * HID];
// attention split-K partials
__device__ float g_op[KSPLIT * TOKENS * DIM];        // unnormalized O partials
__device__ float g_l[KSPLIT * 2 * HEADS * 4096];     // row-sum partials
// attention-native qkv layouts (all bf16)
__device__ __nv_bfloat16 g_qs[2 * HEADS * 4096 * 64];   // [b,h,tok,d] scaled q
__device__ __nv_bfloat16 g_ks[2 * HEADS * 4096 * 64];   // [b,h,tok,d]
__device__ __nv_bfloat16 g_vt[2 * HEADS * 64 * 4096];   // [b,h,d,kv]
// pre-rounded (tf32) weights: qkv_w | proj_w | fc1_w | fc2_w
#define W_QKV_OFF 0
#define W_PROJ_OFF 442368
#define W_FC1_OFF (442368 + 147456)
#define W_FC2_OFF (442368 + 147456 + 589824)
#define W_TOTAL (442368 + 147456 + 589824 + 589824)
__device__ float g_w[W_TOTAL];

// ---------------- helpers ------------------------------------------------------
__device__ __forceinline__ uint32_t f2tf(float x) {
    uint32_t u;
    asm("cvt.rna.tf32.f32 %0, %1;" : "=r"(u) : "f"(x));
    return u;
}
__device__ __forceinline__ float rnd_tf(float x) {
    return __uint_as_float(f2tf(x));
}
__device__ __forceinline__ uint32_t pack_bf2(float lo, float hi) {
    uint32_t r;
    asm("cvt.rn.bf16x2.f32 %0, %1, %2;" : "=r"(r) : "f"(hi), "f"(lo));
    return r;
}

__device__ __forceinline__ uint32_t smem_u32(const void* p) {
    uint32_t a;
    asm("{ .reg .u64 t; cvta.to.shared.u64 t, %1; cvt.u32.u64 %0, t; }"
        : "=r"(a) : "l"(p));
    return a;
}

__device__ __forceinline__ void mma_tf32(float c[4], const uint32_t a[4],
                                         const uint32_t b[2]) {
    asm volatile(
        "mma.sync.aligned.m16n8k8.row.col.f32.tf32.tf32.f32 "
        "{%0,%1,%2,%3}, {%4,%5,%6,%7}, {%8,%9}, {%0,%1,%2,%3};"
        : "+f"(c[0]), "+f"(c[1]), "+f"(c[2]), "+f"(c[3])
        : "r"(a[0]), "r"(a[1]), "r"(a[2]), "r"(a[3]), "r"(b[0]), "r"(b[1]));
}
__device__ __forceinline__ void mma_bf16(float c[4], const uint32_t a[4],
                                         const uint32_t b[2]) {
    asm volatile(
        "mma.sync.aligned.m16n8k16.row.col.f32.bf16.bf16.f32 "
        "{%0,%1,%2,%3}, {%4,%5,%6,%7}, {%8,%9}, {%0,%1,%2,%3};"
        : "+f"(c[0]), "+f"(c[1]), "+f"(c[2]), "+f"(c[3])
        : "r"(a[0]), "r"(a[1]), "r"(a[2]), "r"(a[3]), "r"(b[0]), "r"(b[1]));
}
__device__ __forceinline__ void ldsm4(uint32_t r[4], uint32_t addr) {
    asm volatile(
        "ldmatrix.sync.aligned.m8n8.x4.shared.b16 {%0,%1,%2,%3}, [%4];"
        : "=r"(r[0]), "=r"(r[1]), "=r"(r[2]), "=r"(r[3]) : "r"(addr));
}

// ---------------- fused weight pre-round (single launch) ----------------------
__global__ void round_w_all(const float* __restrict__ w0, const float* __restrict__ w1,
                            const float* __restrict__ w2, const float* __restrict__ w3,
                            float* __restrict__ out) {
    int i = blockIdx.x * 256 + threadIdx.x;  // float4 index
    const int n0 = W_PROJ_OFF / 4, n1 = W_FC1_OFF / 4, n2 = W_FC2_OFF / 4,
              n3 = W_TOTAL / 4;
    if (i >= n3) return;
    float4 v;
    if (i < n0)      v = ((const float4*)w0)[i];
    else if (i < n1) v = ((const float4*)w1)[i - n0];
    else if (i < n2) v = ((const float4*)w2)[i - n1];
    else             v = ((const float4*)w3)[i - n2];
    ((float4*)out)[i] =
        make_float4(rnd_tf(v.x), rnd_tf(v.y), rnd_tf(v.z), rnd_tf(v.w));
}

// ---------------- LayerNorm (outputs tf32-rounded: feeds GEMM A operand) ------
__global__ void ln_kernel(const float* __restrict__ in, const float* __restrict__ w,
                          const float* __restrict__ b, float* __restrict__ out) {
    int row = blockIdx.x;
    const float* x = in + (size_t)row * DIM;
    int t = threadIdx.x;  // 128
    float v0 = x[t], v1 = x[t + 128], v2 = x[t + 256];
    float s = v0 + v1 + v2;
    float q = v0 * v0 + v1 * v1 + v2 * v2;
#pragma unroll
    for (int off = 16; off; off >>= 1) {
        s += __shfl_xor_sync(0xffffffffu, s, off);
        q += __shfl_xor_sync(0xffffffffu, q, off);
    }
    __shared__ float ss[4], sq[4];
    int wid = t >> 5, lane = t & 31;
    if (lane == 0) { ss[wid] = s; sq[wid] = q; }
    __syncthreads();
    s = ss[0] + ss[1] + ss[2] + ss[3];
    q = sq[0] + sq[1] + sq[2] + sq[3];
    float mean = s * (1.0f / DIM);
    float var = q * (1.0f / DIM) - mean * mean;
    float rstd = rsqrtf(var + 1e-5f);
    float* o = out + (size_t)row * DIM;
    o[t]       = rnd_tf((v0 - mean) * rstd * w[t]       + b[t]);
    o[t + 128] = rnd_tf((v1 - mean) * rstd * w[t + 128] + b[t + 128]);
    o[t + 256] = rnd_tf((v2 - mean) * rstd * w[t + 256] + b[t + 256]);
}

// ---------------- cp.async tf32 GEMM: C = A[M,K] * B[N,K]^T (+epi) -----------
enum { EPI_QKV = 0, EPI_BIAS_RES = 1, EPI_GELU = 2, EPI_OUT2 = 3 };

#define GBM 128
#define GBN 128
#define GBK 32
#define GSTAGES 3
#define GBOFF (GBM * 36 * 4)
#define GSTRIDE ((GBM + GBN) * 36 * 4)
#define GEMM_SMEM (GSTAGES * GSTRIDE)

template <int EPI>
__global__ void __launch_bounds__(256, 2)
gemm_cp(const float* __restrict__ A, const float* __restrict__ B,
        const float* __restrict__ bias, const float* __restrict__ res,
        float* __restrict__ C, __nv_bfloat16* __restrict__ Cq,
        __nv_bfloat16* __restrict__ Ck, __nv_bfloat16* __restrict__ Cv,
        int M, int N, int K) {
    extern __shared__ char smem[];
    uint32_t sb = smem_u32(smem);
    int tid = threadIdx.x;
    int bm = blockIdx.y * GBM, bn = blockIdx.x * GBN;
    int wid = tid >> 5, lane = tid & 31;
    int wm = (wid & 1) * 64, wn = (wid >> 1) * 32;
    int g = lane >> 2, t4 = lane & 3;

    int lr = tid >> 3;
    int lq = (tid & 7) * 4;

    const float* Ap = A + (size_t)(bm + lr) * K + lq;
    const float* Bp = B + (size_t)(bn + lr) * K + lq;
    uint32_t dA = sb + (uint32_t)(lr * 36 + lq) * 4;
    uint32_t dB = sb + GBOFF + (uint32_t)(lr * 36 + lq) * 4;

    const int S = K / GBK;

#define G_ISSUE(st)                                                            \
    do {                                                                       \
        uint32_t off = (uint32_t)((st) % GSTAGES) * GSTRIDE;                   \
        int k0 = (st) * GBK;                                                   \
        _Pragma("unroll")                                                      \
        for (int i = 0; i < 4; i++)                                            \
            asm volatile("cp.async.cg.shared.global [%0], [%1], 16;"           \
                         :: "r"(dA + off + (uint32_t)(i * 32 * 36 * 4)),       \
                            "l"(Ap + (size_t)(32 * i) * K + k0) : "memory");   \
        _Pragma("unroll")                                                      \
        for (int i = 0; i < 4; i++)                                            \
            asm volatile("cp.async.cg.shared.global [%0], [%1], 16;"           \
                         :: "r"(dB + off + (uint32_t)(i * 32 * 36 * 4)),       \
                            "l"(Bp + (size_t)(32 * i) * K + k0) : "memory");   \
        asm volatile("cp.async.commit_group;" ::: "memory");                   \
    } while (0)

    G_ISSUE(0);
    G_ISSUE(1);

    float c[4][4][4] = {};

    for (int s = 0; s < S; s++) {
        asm volatile("cp.async.wait_group %0;" :: "n"(GSTAGES - 2) : "memory");
        __syncthreads();
        if (s + GSTAGES - 1 < S) G_ISSUE(s + GSTAGES - 1);

        const float(*As)[36] =
            (const float(*)[36])(smem + (s % GSTAGES) * GSTRIDE);
        const float(*Bs)[36] =
            (const float(*)[36])(smem + (s % GSTAGES) * GSTRIDE + GBOFF);

#pragma unroll
        for (int ks = 0; ks < 4; ks++) {
            int kk = ks * 8;
            uint32_t a[4][4], b[4][2];
#pragma unroll
            for (int im = 0; im < 4; im++) {
                int m = wm + im * 16 + g;
                a[im][0] = __float_as_uint(As[m][kk + t4]);
                a[im][1] = __float_as_uint(As[m + 8][kk + t4]);
                a[im][2] = __float_as_uint(As[m][kk + t4 + 4]);
                a[im][3] = __float_as_uint(As[m + 8][kk + t4 + 4]);
            }
#pragma unroll
            for (int jn = 0; jn < 4; jn++) {
                int n = wn + jn * 8 + g;
                b[jn][0] = __float_as_uint(Bs[n][kk + t4]);
                b[jn][1] = __float_as_uint(Bs[n][kk + t4 + 4]);
            }
#pragma unroll
            for (int im = 0; im < 4; im++)
#pragma unroll
                for (int jn = 0; jn < 4; jn++) mma_tf32(c[im][jn], a[im], b[jn]);
        }
    }

    // epilogue
#pragma unroll
    for (int im = 0; im < 4; im++) {
#pragma unroll
        for (int half = 0; half < 2; half++) {
            int row = bm + wm + im * 16 + g + half * 8;
#pragma unroll
            for (int jn = 0; jn < 4; jn++) {
                int col = bn + wn + jn * 8 + t4 * 2;
                float v0 = c[im][jn][2 * half];
                float v1 = c[im][jn][2 * half + 1];
                if (EPI == EPI_QKV) {
                    int b = row >> 12, tok = row & 4095;
                    if (col < 768) {
                        bool isq = col < 384;
                        float sc = isq ? 0.125f : 1.0f;
                        int cc = isq ? col : col - 384;
                        int h = cc >> 6, d = cc & 63;
                        __nv_bfloat16* dst = isq ? Cq : Ck;
                        *(uint32_t*)&dst[(((size_t)b * HEADS + h) * 4096 + tok) * 64 + d] =
                            pack_bf2(v0 * sc, v1 * sc);
                    } else {
                        int cc = col - 768;
                        int h = cc >> 6, d = cc & 63;
                        size_t base = (((size_t)b * HEADS + h) * 64 + d) * 4096 + tok;
                        Cv[base]        = __float2bfloat16(v0);
                        Cv[base + 4096] = __float2bfloat16(v1);
                    }
                    continue;
                } else if (EPI == EPI_BIAS_RES) {
                    v0 += bias[col]     + res[(size_t)row * N + col];
                    v1 += bias[col + 1] + res[(size_t)row * N + col + 1];
                } else if (EPI == EPI_GELU) {
                    v0 += bias[col];
                    v1 += bias[col + 1];
                    v0 = rnd_tf(0.5f * v0 * (1.0f + erff(v0 * 0.70710678118654752f)));
                    v1 = rnd_tf(0.5f * v1 * (1.0f + erff(v1 * 0.70710678118654752f)));
                } else if (EPI == EPI_OUT2) {
                    v0 = 2.0f * (v0 + bias[col]);
                    v1 = 2.0f * (v1 + bias[col + 1]);
                }
                *(float2*)&C[(size_t)row * N + col] = make_float2(v0, v1);
            }
        }
    }
}

// ---------------- flash attention v5: R15 shape + split-K over KV -------------
// 4 warps x 32q, 128q CTA (proven best per-warp shape). gridDim.z = KV split;
// each CTA covers 2048 kv (32 tiles), emits UNNORMALIZED O + row-sum partials.
#define AT_QS 0                           // 128*144 = 18432
#define AT_KS 18432                       // 2 * 9216
#define AT_VT (18432 + 18432)             // 2 * 9216
#define ATTN_SMEM (AT_VT + 18432)         // 55296
#define TILES_PER_SPLIT (64 / KSPLIT)

__global__ void __launch_bounds__(128, 3)
attn_tc(const __nv_bfloat16* __restrict__ qg, const __nv_bfloat16* __restrict__ kg,
        const __nv_bfloat16* __restrict__ vg, float* __restrict__ op,
        float* __restrict__ lv) {
    extern __shared__ char sm[];
    uint32_t sb = smem_u32(sm);
    uint16_t* Qs = (uint16_t*)(sm + AT_QS);

    int bh = blockIdx.y;
    int b = bh / HEADS, h = bh % HEADS;
    int q0 = blockIdx.x * 128;
    int split = blockIdx.z;
    int kt0 = split * TILES_PER_SPLIT;
    int tid = threadIdx.x;
    int wid = tid >> 5, lane = tid & 31;
    int wm = wid * 32;  // 32 q rows per warp
    int g = lane >> 2, t4 = lane & 3;

    const __nv_bfloat16* qb = qg + (((size_t)bh * 4096) + q0) * 64;
    const __nv_bfloat16* kb = kg + (size_t)bh * 4096 * 64;
    const __nv_bfloat16* vb = vg + (size_t)bh * 64 * 4096;

    // stage Q (128 rows x 64 bf16, rows padded to 72 halves)
#pragma unroll
    for (int i = 0; i < 8; i++) {
        int chunk = tid + 128 * i;
        int row = chunk >> 3, c8 = (chunk & 7) * 8;
        *(uint4*)(Qs + row * 72 + c8) = *(const uint4*)(qb + row * 64 + c8);
    }

    // cp.async staging of K / Vt bf16 64x64 tiles, double-buffered
    int srow = tid >> 1, shalf = tid & 1;
    uint32_t kdst = sb + AT_KS + (uint32_t)(srow * 144 + shalf * 64);
    const __nv_bfloat16* ksrc0 = kb + (size_t)srow * 64 + shalf * 32;
    uint32_t vdst = sb + AT_VT + (uint32_t)(srow * 144 + shalf * 64);
    const __nv_bfloat16* vsrc0 = vb + (size_t)srow * 4096 + shalf * 32;

#define AT_ISSUE(kt, p)                                                        \
    do {                                                                       \
        const __nv_bfloat16* ks_ = ksrc0 + (size_t)(kt) * 64 * 64;             \
        uint32_t kd_ = kdst + (uint32_t)(p) * 9216u;                           \
        const __nv_bfloat16* vs_ = vsrc0 + (size_t)(kt) * 64;                  \
        uint32_t vd_ = vdst + (uint32_t)(p) * 9216u;                           \
        _Pragma("unroll")                                                      \
        for (int i = 0; i < 4; i++) {                                          \
            asm volatile("cp.async.cg.shared.global [%0], [%1], 16;"           \
                         :: "r"(kd_ + (uint32_t)(i * 16)),                     \
                            "l"(ks_ + i * 8) : "memory");                      \
            asm volatile("cp.async.cg.shared.global [%0], [%1], 16;"           \
                         :: "r"(vd_ + (uint32_t)(i * 16)),                     \
                            "l"(vs_ + i * 8) : "memory");                      \
        }                                                                      \
        asm volatile("cp.async.commit_group;" ::: "memory");                   \
    } while (0)

    AT_ISSUE(kt0, 0);
    __syncthreads();  // Q staged

    // ldmatrix lane offsets (rows * 144B, col-halves * 2B)
    uint32_t aoff = (uint32_t)(((lane & 7) + ((lane >> 3) & 1) * 8) * 144 +
                               (lane >> 4) * 16);
    uint32_t boff = (uint32_t)((((lane >> 4) & 1) * 8 + (lane & 7)) * 144 +
                               ((lane >> 3) & 1) * 16);

    // load Q fragments once (tile-invariant): qa[im][ks][4]
    uint32_t qa[2][4][4];
#pragma unroll
    for (int im = 0; im < 2; im++)
#pragma unroll
        for (int ks = 0; ks < 4; ks++)
            ldsm4(qa[im][ks],
                  sb + AT_QS + (uint32_t)((wm + im * 16) * 144 + ks * 32) + aoff);

    float o[2][8][4] = {};
    float lacc[2][2] = {};

    for (int t = 0; t < TILES_PER_SPLIT; t++) {
        int p = t & 1;
        asm volatile("cp.async.wait_group 0;" ::: "memory");
        __syncthreads();  // tile ready; prev tile's reads done everywhere
        if (t < TILES_PER_SPLIT - 1) AT_ISSUE(kt0 + t + 1, p ^ 1);

        uint32_t kbase = sb + AT_KS + (uint32_t)p * 9216u + boff;
        uint32_t vbase = sb + AT_VT + (uint32_t)p * 9216u + boff;

#pragma unroll
        for (int qq = 0; qq < 4; qq++) {  // kv quarter: cols 16*qq..+15
            float scq[2][2][4] = {};
#pragma unroll
            for (int ks = 0; ks < 4; ks++) {
                uint32_t kb4[4];
                ldsm4(kb4, kbase + (uint32_t)(qq * 16 * 144 + ks * 32));
#pragma unroll
                for (int im = 0; im < 2; im++) {
                    mma_bf16(scq[im][0], qa[im][ks], kb4 + 0);
                    mma_bf16(scq[im][1], qa[im][ks], kb4 + 2);
                }
            }
            uint32_t pp[2][4];
#pragma unroll
            for (int im = 0; im < 2; im++) {
#pragma unroll
                for (int jl = 0; jl < 2; jl++) {
                    float e0 = __expf(scq[im][jl][0]);
                    float e1 = __expf(scq[im][jl][1]);
                    float e2 = __expf(scq[im][jl][2]);
                    float e3 = __expf(scq[im][jl][3]);
                    lacc[im][0] += e0 + e1;
                    lacc[im][1] += e2 + e3;
                    pp[im][jl * 2 + 0] = pack_bf2(e0, e1);   // row g
                    pp[im][jl * 2 + 1] = pack_bf2(e2, e3);   // row g+8
                }
            }
#pragma unroll
            for (int dj = 0; dj < 4; dj++) {  // d-group pairs (2dj, 2dj+1)
                uint32_t vb4[4];
                ldsm4(vb4, vbase + (uint32_t)(dj * 16 * 144 + qq * 32));
#pragma unroll
                for (int im = 0; im < 2; im++) {
                    mma_bf16(o[im][2 * dj + 0], pp[im], vb4 + 0);
                    mma_bf16(o[im][2 * dj + 1], pp[im], vb4 + 2);
                }
            }
        }
    }

    // deferred row-sum quad reduction (rows are warp-private)
#pragma unroll
    for (int im = 0; im < 2; im++)
#pragma unroll
        for (int hf = 0; hf < 2; hf++) {
            float s = lacc[im][hf];
            s += __shfl_xor_sync(0xffffffffu, s, 1);
            s += __shfl_xor_sync(0xffffffffu, s, 2);
            lacc[im][hf] = s;
        }

    // epilogue: write UNNORMALIZED partials
    float* opb = op + (size_t)split * TOKENS * DIM;
    float* lvb = lv + (size_t)split * 2 * HEADS * 4096;
#pragma unroll
    for (int im = 0; im < 2; im++) {
#pragma unroll
        for (int hf = 0; hf < 2; hf++) {
            int row = q0 + wm + im * 16 + g + hf * 8;
            if (t4 == 0) lvb[(size_t)bh * 4096 + row] = lacc[im][hf];
#pragma unroll
            for (int dg = 0; dg < 8; dg++) {
                int col = h * 64 + dg * 8 + t4 * 2;
                *(float2*)&opb[((size_t)b * 4096 + row) * DIM + col] =
                    make_float2(o[im][dg][2 * hf], o[im][dg][2 * hf + 1]);
            }
        }
    }
}

// ---------------- split-K combine: normalize + tf32 pre-round -----------------
__global__ void __launch_bounds__(96)
attn_combine(const float* __restrict__ op, const float* __restrict__ lv,
             float* __restrict__ out) {
    int row = blockIdx.x;           // 0..8191 (b*4096 + tok)
    int b = row >> 12, tok = row & 4095;
    int c = threadIdx.x * 4;        // col group
    int h = c >> 6;
    size_t li = ((size_t)b * HEADS + h) * 4096 + tok;
    float l = lv[li] + lv[2 * HEADS * 4096 + li];
    float inv = 1.0f / l;
    size_t idx = (size_t)row * DIM + c;
    float4 a = *(const float4*)&op[idx];
    float4 d = *(const float4*)&op[(size_t)TOKENS * DIM + idx];
    *(float4*)&out[idx] = make_float4(
        rnd_tf((a.x + d.x) * inv), rnd_tf((a.y + d.y) * inv),
        rnd_tf((a.z + d.z) * inv), rnd_tf((a.w + d.w) * inv));
}

// ---------------- launch --------------------------------------------------------
extern "C" void kernel_launch(void* const* d_in, const int* in_sizes, int n_in,
                              void* d_out, int out_size) {
    (void)in_sizes; (void)n_in; (void)out_size;
    const float* x      = (const float*)d_in[0];
    const float* qkv_w  = (const float*)d_in[1];
    const float* proj_w = (const float*)d_in[2];
    const float* proj_b = (const float*)d_in[3];
    const float* ln1_w  = (const float*)d_in[4];
    const float* ln1_b  = (const float*)d_in[5];
    const float* ln2_w  = (const float*)d_in[6];
    const float* ln2_b  = (const float*)d_in[7];
    const float* fc1_w  = (const float*)d_in[8];
    const float* fc1_b  = (const float*)d_in[9];
    const float* fc2_w  = (const float*)d_in[10];
    const float* fc2_b  = (const float*)d_in[11];
    float* out = (float*)d_out;

    float *y, *attn, *res, *hbuf, *wbuf, *opb, *lvb;
    __nv_bfloat16 *qs, *ks, *vt;
    cudaGetSymbolAddress((void**)&y, g_y);
    cudaGetSymbolAddress((void**)&attn, g_attn);
    cudaGetSymbolAddress((void**)&res, g_res);
    cudaGetSymbolAddress((void**)&hbuf, g_h);
    cudaGetSymbolAddress((void**)&wbuf, g_w);
    cudaGetSymbolAddress((void**)&opb, g_op);
    cudaGetSymbolAddress((void**)&lvb, g_l);
    cudaGetSymbolAddress((void**)&qs, g_qs);
    cudaGetSymbolAddress((void**)&ks, g_ks);
    cudaGetSymbolAddress((void**)&vt, g_vt);

    float* w_qkv  = wbuf + W_QKV_OFF;
    float* w_proj = wbuf + W_PROJ_OFF;
    float* w_fc1  = wbuf + W_FC1_OFF;
    float* w_fc2  = wbuf + W_FC2_OFF;

    cudaFuncSetAttribute(attn_tc, cudaFuncAttributeMaxDynamicSharedMemorySize,
                         ATTN_SMEM);
    cudaFuncSetAttribute(gemm_cp<EPI_QKV>,
                         cudaFuncAttributeMaxDynamicSharedMemorySize, GEMM_SMEM);
    cudaFuncSetAttribute(gemm_cp<EPI_BIAS_RES>,
                         cudaFuncAttributeMaxDynamicSharedMemorySize, GEMM_SMEM);
    cudaFuncSetAttribute(gemm_cp<EPI_GELU>,
                         cudaFuncAttributeMaxDynamicSharedMemorySize, GEMM_SMEM);
    cudaFuncSetAttribute(gemm_cp<EPI_OUT2>,
                         cudaFuncAttributeMaxDynamicSharedMemorySize, GEMM_SMEM);

    // 0) pre-round all weights to tf32 in one launch
    round_w_all<<<(W_TOTAL / 4 + 255) / 256, 256>>>(qkv_w, proj_w, fc1_w, fc2_w,
                                                    wbuf);

    // 1) LN1 (rounded out)
    ln_kernel<<<TOKENS, 128>>>(x, ln1_w, ln1_b, y);
    // 2) qkv = y @ qkv_w^T -> q[b,h,t,d] bf16 (scaled), k[b,h,t,d] bf16, vt[b,h,d,t] bf16
    gemm_cp<EPI_QKV><<<dim3(1152 / GBN, TOKENS / GBM), 256, GEMM_SMEM>>>(
        y, w_qkv, nullptr, nullptr, nullptr, qs, ks, vt, TOKENS, 3 * DIM, DIM);
    // 3) flash attention split-K partials, then combine -> g_attn (rounded)
    attn_tc<<<dim3(32, 12, KSPLIT), 128, ATTN_SMEM>>>(qs, ks, vt, opb, lvb);
    attn_combine<<<TOKENS, 96>>>(opb, lvb, attn);
    // 4) res = x + attn @ proj_w^T + proj_b
    gemm_cp<EPI_BIAS_RES><<<dim3(DIM / GBN, TOKENS / GBM), 256, GEMM_SMEM>>>(
        attn, w_proj, proj_b, x, res, nullptr, nullptr, nullptr, TOKENS, DIM, DIM);
    // 5) LN2 (rounded out)
    ln_kernel<<<TOKENS, 128>>>(res, ln2_w, ln2_b, y);
    // 6) h = gelu(y @ fc1_w^T + fc1_b)  (rounded out)
    gemm_cp<EPI_GELU><<<dim3(HID / GBN, TOKENS / GBM), 256, GEMM_SMEM>>>(
        y, w_fc1, fc1_b, nullptr, hbuf, nullptr, nullptr, nullptr, TOKENS, HID, DIM);
    // 7) out = 2 * (h @ fc2_w^T + fc2_b)
    gemm_cp<EPI_OUT2><<<dim3(DIM / GBN, TOKENS / GBM), 256, GEMM_SMEM>>>(
        hbuf, w_fc2, fc2_b, nullptr, out, nullptr, nullptr, nullptr, TOKENS, DIM, HID);
}